// round 11
// baseline (speedup 1.0000x reference)
#include <cuda_runtime.h>
#include <cstdint>

#define C_MAX   256
#define N_MAX   65536
#define D_MAXEL 4096
#define BETA    0.3f
#define PA_ROWS 16
#define DPAD    16      // doubles per class slot (128 B) for moment atomics

// -------- device scratch (static: no allocations allowed; zero-initialized,
// and k_final resets all accumulators so every graph replay starts clean) ----
__device__ float  g_sums[(size_t)C_MAX * D_MAXEL]; // class sums (raw)
__device__ int    g_counts[C_MAX];
__device__ int    g_fill[C_MAX];
__device__ int    g_idx[N_MAX];    // sample index sorted by class
__device__ int    g_slab[N_MAX];   // label at sorted position
__device__ double g_dsum[C_MAX * DPAD];   // per-class sum of d   (padded)
__device__ double g_dsum2[C_MAX * DPAD];  // per-class sum of d^2 (padded)
__device__ int    g_is64;          // labels are int64?
__device__ int    g_C;

__device__ __forceinline__ int get_label(const void* labels, int i, int is64) {
    if (is64) return (int)((const long long*)labels)[i];
    return ((const int*)labels)[i];
}

// ============================================================================
// Kernel 1: zero class sums + per-block dtype detect + histogram.
// ============================================================================
__global__ void k_pre(const void* labels, const void* ncls, int N, int total4) {
    int tid = threadIdx.x;

    // per-block dtype detect: sample the first 256 odd 32-bit words.
    // int32 labels -> odd words are labels (uniform in [0,C)); all-zero ~ impossible.
    __shared__ int sh_bad;
    if (tid == 0) sh_bad = 0;
    __syncthreads();
    {
        const int* w = (const int*)labels;
        int half = N / 2;
        int samples = half < 256 ? half : 256;
        int bad = 0;
        for (int s = tid; s < samples; s += blockDim.x)
            if (w[2 * s + 1] != 0) bad = 1;
        if (bad) sh_bad = 1;
    }
    __syncthreads();
    int is64 = !sh_bad;
    if (blockIdx.x == 0 && tid == 0) {
        g_is64 = is64;
        int c = 100;
        if (ncls) c = ((const int*)ncls)[0];
        if (c < 1 || c > C_MAX) c = 100;
        g_C = c;
    }

    // zero class sums (grid-stride; consumed only by the later k_sums)
    for (int idx = blockIdx.x * blockDim.x + tid; idx < total4;
         idx += gridDim.x * blockDim.x)
        ((float4*)g_sums)[idx] = make_float4(0.f, 0.f, 0.f, 0.f);

    // histogram with shared pre-aggregation
    __shared__ int h[C_MAX];
    h[tid] = 0;                               // blockDim.x == 256 == C_MAX
    __syncthreads();
    for (int i = blockIdx.x * blockDim.x + tid; i < N; i += gridDim.x * blockDim.x) {
        int l = get_label(labels, i, is64);
        atomicAdd(&h[l], 1);
    }
    __syncthreads();
    if (h[tid]) atomicAdd(&g_counts[tid], h[tid]);
}

// One block (C_MAX threads): exclusive scan -> fill cursors.
__global__ void k_scan() {
    __shared__ int tmp[C_MAX];
    int t = threadIdx.x;
    int v = g_counts[t];
    tmp[t] = v;
    __syncthreads();
    #pragma unroll
    for (int o = 1; o < C_MAX; o <<= 1) {
        int x = (t >= o) ? tmp[t - o] : 0;
        __syncthreads();
        tmp[t] += x;
        __syncthreads();
    }
    g_fill[t] = tmp[t] - v;
}

// 3-phase shared pre-aggregation scatter (proven structure).
__global__ void k_scatter(const void* labels, int N) {
    __shared__ int base[C_MAX];
    __shared__ int cnt1[C_MAX];
    __shared__ int cnt2[C_MAX];
    for (int i = threadIdx.x; i < C_MAX; i += blockDim.x) { cnt1[i] = 0; cnt2[i] = 0; }
    __syncthreads();
    int is64 = g_is64;
    int i = blockIdx.x * blockDim.x + threadIdx.x;
    int l = -1;
    if (i < N) {
        l = get_label(labels, i, is64);
        atomicAdd(&cnt1[l], 1);
    }
    __syncthreads();
    for (int c = threadIdx.x; c < C_MAX; c += blockDim.x)
        if (cnt1[c]) base[c] = atomicAdd(&g_fill[c], cnt1[c]);
    __syncthreads();
    if (i < N) {
        int r = atomicAdd(&cnt2[l], 1);
        int pos = base[l] + r;
        g_idx[pos] = i;
        g_slab[pos] = l;
    }
}

// ============================================================================
// Pass A: class sums over class-sorted rows, ONE float4 column per thread
// (256 threads), PA_ROWS=16, unroll 8 -> deep row-load pipeline per thread.
// ============================================================================
__global__ void k_sums(const float4* __restrict__ emb, int N, int D4) {
    __shared__ int s_idx[PA_ROWS];
    __shared__ int s_run[PA_ROWS + 1];
    __shared__ int s_cls[PA_ROWS];
    __shared__ int s_nruns;

    int p0 = blockIdx.x * PA_ROWS;
    int n = min(PA_ROWS, N - p0);
    if (threadIdx.x < n) s_idx[threadIdx.x] = g_idx[p0 + threadIdx.x];
    if (threadIdx.x == 0) {
        int nr = 0, cur = -1;
        for (int j = 0; j < n; j++) {
            int c = g_slab[p0 + j];
            if (c != cur) { s_run[nr] = j; s_cls[nr] = c; nr++; cur = c; }
        }
        s_run[nr] = n;
        s_nruns = nr;
    }
    __syncthreads();

    int col = blockIdx.y * blockDim.x + threadIdx.x; // float4 column
    if (col >= D4) return;
    int D = D4 * 4;
    int nruns = s_nruns;
    for (int r = 0; r < nruns; r++) {
        int a = s_run[r], b = s_run[r + 1];
        float4 acc = make_float4(0.f, 0.f, 0.f, 0.f);
        #pragma unroll 8
        for (int j = a; j < b; j++) {
            float4 v = emb[(size_t)s_idx[j] * D4 + col];
            acc.x += v.x; acc.y += v.y; acc.z += v.z; acc.w += v.w;
        }
        float* dst = &g_sums[(size_t)s_cls[r] * D + col * 4];
        atomicAdd(dst + 0, acc.x);
        atomicAdd(dst + 1, acc.y);
        atomicAdd(dst + 2, acc.z);
        atomicAdd(dst + 3, acc.w);
    }
}

// ============================================================================
// Pass B: natural-order per-sample squared distance; fully-unrolled exact
// trip count -> all row loads in flight; per-class double moment atomics.
// ============================================================================
__global__ void k_dist(const float4* __restrict__ emb, const void* labels,
                       int N, int D4) {
    int w = threadIdx.x >> 5, lane = threadIdx.x & 31;
    int i = blockIdx.x * (blockDim.x >> 5) + w;
    if (i >= N) return;
    const float4* e = emb + (size_t)i * D4 + lane;  // address independent of labels
    int l = get_label(labels, i, g_is64);
    float inv = 1.f / (float)max(g_counts[l], 1);
    const float4* c = (const float4*)g_sums + (size_t)l * D4 + lane;
    int iters = D4 >> 5; // D4 multiple of 32 for this problem
    float s = 0.f;
    #pragma unroll
    for (int t = 0; t < 8; t++) {       // fast path when iters == 8 (D == 1024)
        if (t >= iters) break;
        float4 a = e[t * 32];
        float4 b = c[t * 32];
        float dx = a.x - b.x * inv;
        float dy = a.y - b.y * inv;
        float dz = a.z - b.z * inv;
        float dw = a.w - b.w * inv;
        s = fmaf(dx, dx, s);
        s = fmaf(dy, dy, s);
        s = fmaf(dz, dz, s);
        s = fmaf(dw, dw, s);
    }
    for (int t = 8; t < iters; t++) {   // generic remainder (not hit for D=1024)
        float4 a = e[t * 32];
        float4 b = c[t * 32];
        float dx = a.x - b.x * inv;
        float dy = a.y - b.y * inv;
        float dz = a.z - b.z * inv;
        float dw = a.w - b.w * inv;
        s = fmaf(dx, dx, s);
        s = fmaf(dy, dy, s);
        s = fmaf(dz, dz, s);
        s = fmaf(dw, dw, s);
    }
    #pragma unroll
    for (int o = 16; o; o >>= 1) s += __shfl_down_sync(0xffffffffu, s, o);
    if (lane == 0) {
        double d = (double)s;
        atomicAdd(&g_dsum[l * DPAD], d);
        atomicAdd(&g_dsum2[l * DPAD], d * d);
    }
}

// ============================================================================
// Final: per-class variance from moments, loss, n_present, output; reset
// accumulators for the next graph replay.
// ============================================================================
__global__ void k_final(float* out) {
    __shared__ double sh_loss;
    __shared__ int sh_np;
    int t = threadIdx.x;
    if (t == 0) { sh_loss = 0.0; sh_np = 0; }
    __syncthreads();
    int C = g_C;
    if (t < C) {
        int cnt = g_counts[t];
        if (cnt > 0) atomicAdd(&sh_np, 1);
        if (cnt > 1) {
            double sd = g_dsum[t * DPAD];
            double sd2 = g_dsum2[t * DPAD];
            double var = (sd2 - sd * sd / (double)cnt) / (double)(cnt - 1);
            atomicAdd(&sh_loss, var);
        }
    }
    __syncthreads();
    if (t == 0) {
        double np = (double)(sh_np > 0 ? sh_np : 1);
        out[0] = (float)((double)BETA * sh_loss / np);
    }
    // reset accumulators for deterministic replays
    g_counts[t] = 0;
    #pragma unroll
    for (int k = 0; k < DPAD; k++) {
        g_dsum[t * DPAD + k] = 0.0;
        g_dsum2[t * DPAD + k] = 0.0;
    }
}

// -------- launch --------
extern "C" void kernel_launch(void* const* d_in, const int* in_sizes, int n_in,
                              void* d_out, int out_size) {
    const float* emb = (const float*)d_in[0];
    const void*  lab = d_in[1];
    const void*  ncl = (n_in >= 3) ? d_in[2] : nullptr;
    float* out = (float*)d_out;

    int N = in_sizes[1];
    int D = in_sizes[0] / N;
    int D4 = D / 4;                       // D multiple of 4 for this problem
    int total4 = C_MAX * D4;

    k_pre<<<64, 256>>>(lab, ncl, N, total4);
    k_scan<<<1, C_MAX>>>();
    k_scatter<<<(N + 127) / 128, 128>>>(lab, N);

    dim3 gA((N + PA_ROWS - 1) / PA_ROWS, (D4 + 255) / 256);
    k_sums<<<gA, 256>>>((const float4*)emb, N, D4);

    int wpb = 8; // warps per block
    k_dist<<<(N + wpb - 1) / wpb, wpb * 32>>>((const float4*)emb, lab, N, D4);
    k_final<<<1, C_MAX>>>(out);
}

// round 12
// speedup vs baseline: 1.2000x; 1.2000x over previous
#include <cuda_runtime.h>
#include <cstdint>

#define C_MAX   256
#define N_MAX   65536
#define D_MAXEL 4096
#define BETA    0.3f
#define PA_ROWS 32
#define DPAD    16      // doubles per class slot (128 B) for moment atomics

// -------- device scratch (static: no allocations allowed; zero-initialized,
// and k_final resets all accumulators so every graph replay starts clean) ----
__device__ float  g_sums[(size_t)C_MAX * D_MAXEL]; // class sums (raw)
__device__ int    g_counts[C_MAX];
__device__ int    g_fill[C_MAX];   // within-class cursor, starts at 0 each replay
__device__ int    g_idx[N_MAX];    // sample index sorted by class
__device__ int    g_slab[N_MAX];   // label at sorted position
__device__ double g_dsum[C_MAX * DPAD];   // per-class sum of d   (padded)
__device__ double g_dsum2[C_MAX * DPAD];  // per-class sum of d^2 (padded)
__device__ int    g_is64;          // labels are int64?
__device__ int    g_C;

__device__ __forceinline__ int get_label(const void* labels, int i, int is64) {
    if (is64) return (int)((const long long*)labels)[i];
    return ((const int*)labels)[i];
}

// ============================================================================
// Kernel 1: zero class sums + per-block dtype detect + histogram.
// ============================================================================
__global__ void k_pre(const void* labels, const void* ncls, int N, int total4) {
    int tid = threadIdx.x;

    // per-block dtype detect: sample the first 256 odd 32-bit words.
    // int32 labels -> odd words are labels (uniform in [0,C)); all-zero ~ impossible.
    __shared__ int sh_bad;
    if (tid == 0) sh_bad = 0;
    __syncthreads();
    {
        const int* w = (const int*)labels;
        int half = N / 2;
        int samples = half < 256 ? half : 256;
        int bad = 0;
        for (int s = tid; s < samples; s += blockDim.x)
            if (w[2 * s + 1] != 0) bad = 1;
        if (bad) sh_bad = 1;
    }
    __syncthreads();
    int is64 = !sh_bad;
    if (blockIdx.x == 0 && tid == 0) {
        g_is64 = is64;
        int c = 100;
        if (ncls) c = ((const int*)ncls)[0];
        if (c < 1 || c > C_MAX) c = 100;
        g_C = c;
    }

    // zero class sums (grid-stride; consumed only by the later k_sums)
    for (int idx = blockIdx.x * blockDim.x + tid; idx < total4;
         idx += gridDim.x * blockDim.x)
        ((float4*)g_sums)[idx] = make_float4(0.f, 0.f, 0.f, 0.f);

    // histogram with shared pre-aggregation
    __shared__ int h[C_MAX];
    h[tid] = 0;                               // blockDim.x == 256 == C_MAX
    __syncthreads();
    for (int i = blockIdx.x * blockDim.x + tid; i < N; i += gridDim.x * blockDim.x) {
        int l = get_label(labels, i, is64);
        atomicAdd(&h[l], 1);
    }
    __syncthreads();
    if (h[tid]) atomicAdd(&g_counts[tid], h[tid]);
}

// ============================================================================
// Kernel 2: scatter with in-block scan (no separate k_scan launch).
// Every block recomputes the exclusive scan of g_counts in shared (parallel,
// redundant, cheap); g_fill starts at 0 (reset by k_final) and provides the
// within-class chunk base via atomicAdd.
// ============================================================================
__global__ void k_scatter(const void* labels, int N) {
    __shared__ int off[C_MAX];
    __shared__ int tmp[C_MAX];
    __shared__ int base[C_MAX];
    __shared__ int cnt1[C_MAX];
    __shared__ int cnt2[C_MAX];
    int tid = threadIdx.x;                    // blockDim.x == 256 == C_MAX

    // in-block exclusive scan of g_counts
    int v = g_counts[tid];
    tmp[tid] = v;
    cnt1[tid] = 0;
    cnt2[tid] = 0;
    __syncthreads();
    #pragma unroll
    for (int o = 1; o < C_MAX; o <<= 1) {
        int x = (tid >= o) ? tmp[tid - o] : 0;
        __syncthreads();
        tmp[tid] += x;
        __syncthreads();
    }
    off[tid] = tmp[tid] - v;
    __syncthreads();

    int is64 = g_is64;
    int i = blockIdx.x * blockDim.x + tid;
    int l = -1;
    if (i < N) {
        l = get_label(labels, i, is64);
        atomicAdd(&cnt1[l], 1);
    }
    __syncthreads();
    if (cnt1[tid]) base[tid] = off[tid] + atomicAdd(&g_fill[tid], cnt1[tid]);
    __syncthreads();
    if (i < N) {
        int r = atomicAdd(&cnt2[l], 1);
        int pos = base[l] + r;
        g_idx[pos] = i;
        g_slab[pos] = l;
    }
}

// ============================================================================
// Pass A (R9-proven): class sums over class-sorted rows, one float4 column
// per thread, PA_ROWS=32, unroll 4. Run boundaries precomputed in shared.
// ============================================================================
__global__ void k_sums(const float4* __restrict__ emb, int N, int D4) {
    __shared__ int s_idx[PA_ROWS];
    __shared__ int s_run[PA_ROWS + 1];
    __shared__ int s_cls[PA_ROWS];
    __shared__ int s_nruns;

    int p0 = blockIdx.x * PA_ROWS;
    int n = min(PA_ROWS, N - p0);
    if (threadIdx.x < n) s_idx[threadIdx.x] = g_idx[p0 + threadIdx.x];
    if (threadIdx.x == 0) {
        int nr = 0, cur = -1;
        for (int j = 0; j < n; j++) {
            int c = g_slab[p0 + j];
            if (c != cur) { s_run[nr] = j; s_cls[nr] = c; nr++; cur = c; }
        }
        s_run[nr] = n;
        s_nruns = nr;
    }
    __syncthreads();

    int col = blockIdx.y * blockDim.x + threadIdx.x; // float4 column
    if (col >= D4) return;
    int D = D4 * 4;
    int nruns = s_nruns;
    for (int r = 0; r < nruns; r++) {
        int a = s_run[r], b = s_run[r + 1];
        float4 acc = make_float4(0.f, 0.f, 0.f, 0.f);
        #pragma unroll 4
        for (int j = a; j < b; j++) {
            float4 v = emb[(size_t)s_idx[j] * D4 + col];
            acc.x += v.x; acc.y += v.y; acc.z += v.z; acc.w += v.w;
        }
        float* dst = &g_sums[(size_t)s_cls[r] * D + col * 4];
        atomicAdd(dst + 0, acc.x);
        atomicAdd(dst + 1, acc.y);
        atomicAdd(dst + 2, acc.z);
        atomicAdd(dst + 3, acc.w);
    }
}

// ============================================================================
// Pass B (R9-proven): natural-order per-sample squared distance, unroll 4;
// per-class moment accumulation in double (padded slots).
// ============================================================================
__global__ void k_dist(const float4* __restrict__ emb, const void* labels,
                       int N, int D4) {
    int w = threadIdx.x >> 5, lane = threadIdx.x & 31;
    int i = blockIdx.x * (blockDim.x >> 5) + w;
    if (i >= N) return;
    const float4* e = emb + (size_t)i * D4 + lane;  // address independent of labels
    int l = get_label(labels, i, g_is64);
    float inv = 1.f / (float)max(g_counts[l], 1);
    const float4* c = (const float4*)g_sums + (size_t)l * D4 + lane;
    int iters = D4 >> 5; // D4 multiple of 32 for this problem
    float s = 0.f;
    #pragma unroll 4
    for (int t = 0; t < iters; t++) {
        float4 a = e[t * 32];
        float4 b = c[t * 32];
        float dx = a.x - b.x * inv;
        float dy = a.y - b.y * inv;
        float dz = a.z - b.z * inv;
        float dw = a.w - b.w * inv;
        s = fmaf(dx, dx, s);
        s = fmaf(dy, dy, s);
        s = fmaf(dz, dz, s);
        s = fmaf(dw, dw, s);
    }
    #pragma unroll
    for (int o = 16; o; o >>= 1) s += __shfl_down_sync(0xffffffffu, s, o);
    if (lane == 0) {
        double d = (double)s;
        atomicAdd(&g_dsum[l * DPAD], d);
        atomicAdd(&g_dsum2[l * DPAD], d * d);
    }
}

// ============================================================================
// Final: per-class variance from moments, loss, n_present, output; reset
// accumulators (counts, fill cursors, moments) for the next graph replay.
// ============================================================================
__global__ void k_final(float* out) {
    __shared__ double sh_loss;
    __shared__ int sh_np;
    int t = threadIdx.x;
    if (t == 0) { sh_loss = 0.0; sh_np = 0; }
    __syncthreads();
    int C = g_C;
    if (t < C) {
        int cnt = g_counts[t];
        if (cnt > 0) atomicAdd(&sh_np, 1);
        if (cnt > 1) {
            double sd = g_dsum[t * DPAD];
            double sd2 = g_dsum2[t * DPAD];
            double var = (sd2 - sd * sd / (double)cnt) / (double)(cnt - 1);
            atomicAdd(&sh_loss, var);
        }
    }
    __syncthreads();
    if (t == 0) {
        double np = (double)(sh_np > 0 ? sh_np : 1);
        out[0] = (float)((double)BETA * sh_loss / np);
    }
    // reset accumulators for deterministic replays
    g_counts[t] = 0;
    g_fill[t] = 0;
    #pragma unroll
    for (int k = 0; k < DPAD; k++) {
        g_dsum[t * DPAD + k] = 0.0;
        g_dsum2[t * DPAD + k] = 0.0;
    }
}

// -------- launch --------
extern "C" void kernel_launch(void* const* d_in, const int* in_sizes, int n_in,
                              void* d_out, int out_size) {
    const float* emb = (const float*)d_in[0];
    const void*  lab = d_in[1];
    const void*  ncl = (n_in >= 3) ? d_in[2] : nullptr;
    float* out = (float*)d_out;

    int N = in_sizes[1];
    int D = in_sizes[0] / N;
    int D4 = D / 4;                       // D multiple of 4 for this problem
    int total4 = C_MAX * D4;

    k_pre<<<64, 256>>>(lab, ncl, N, total4);
    k_scatter<<<(N + 255) / 256, 256>>>(lab, N);

    dim3 gA((N + PA_ROWS - 1) / PA_ROWS, (D4 + 255) / 256);
    k_sums<<<gA, 256>>>((const float4*)emb, N, D4);

    int wpb = 8; // warps per block
    k_dist<<<(N + wpb - 1) / wpb, wpb * 32>>>((const float4*)emb, lab, N, D4);
    k_final<<<1, C_MAX>>>(out);
}